// round 16
// baseline (speedup 1.0000x reference)
#include <cuda_runtime.h>
#include <cuda_bf16.h>
#include <cuda_fp16.h>

// MedianPool2d 3x3, zero padding, x: [16, 3, 512, 512] fp32.
// v9: one WARP = one full 512-px image row (TX=16/lane). Lane 0 / lane 31
// halos are the image border -> all predicated scalar halo LDGs and x-bounds
// checks are gone; every load is an aligned LDG.128. TY=2 even-odd shared
// vertical pair; packed fp16x2 comparator tree (2 px per min/max op).
// Exact-in-fp16 median-of-9: med3( max3(lo), med3(mid), min3(hi) ).

#define MP_W 512
#define MP_H 512
#define MP_BC 48            // 16 * 3
#define MP_TX 16            // pixels per lane
#define MP_NP 9             // packed half2 regs per row: {c-1,c0},{c1,c2}..{c15,c16}
#define MP_BLK 128          // 4 warps / CTA
#define MP_RP 256           // row-pairs per image channel (H/2)

// Load a full row (this lane's 16 px) and pack odd-aligned half2 vector.
__device__ __forceinline__ void mp_load_row_h2(const float* __restrict__ row,
                                               int lane, __half2 v[MP_NP]) {
    const float* p = row + lane * MP_TX;
    float4 f0 = *(const float4*)(p);
    float4 f1 = *(const float4*)(p + 4);
    float4 f2 = *(const float4*)(p + 8);
    float4 f3 = *(const float4*)(p + 12);
    float left  = __shfl_up_sync(0xffffffffu, f3.w, 1);   // lane-1's c15
    float right = __shfl_down_sync(0xffffffffu, f0.x, 1); // lane+1's c0
    if (lane == 0)  left  = 0.0f;   // image left border (zero pad)
    if (lane == 31) right = 0.0f;   // image right border (zero pad)
    v[0] = __floats2half2_rn(left, f0.x);
    v[1] = __floats2half2_rn(f0.y, f0.z);
    v[2] = __floats2half2_rn(f0.w, f1.x);
    v[3] = __floats2half2_rn(f1.y, f1.z);
    v[4] = __floats2half2_rn(f1.w, f2.x);
    v[5] = __floats2half2_rn(f2.y, f2.z);
    v[6] = __floats2half2_rn(f2.w, f3.x);
    v[7] = __floats2half2_rn(f3.y, f3.z);
    v[8] = __floats2half2_rn(f3.w, right);
}

__device__ __forceinline__ __half2 h2med3(__half2 a, __half2 b, __half2 c) {
    return __hmax2(__hmin2(a, b), __hmin2(__hmax2(a, b), c));
}

// {a.hi, b.lo}
__device__ __forceinline__ __half2 h2shift(__half2 a, __half2 b) {
    return __halves2half2(__high2half(a), __low2half(b));
}

// One output row: insert third row c into shared vertical pair (pm, px),
// packed horizontal combine, fp32 store of 16 px.
__device__ __forceinline__ void mp_emit_row(const __half2 pm[MP_NP],
                                            const __half2 px[MP_NP],
                                            const __half2 c[MP_NP],
                                            float* optr, int lane) {
    __half2 lo[MP_NP], mid[MP_NP], hi[MP_NP];
    #pragma unroll
    for (int i = 0; i < MP_NP; i++) {
        lo[i]  = __hmin2(pm[i], c[i]);
        hi[i]  = __hmax2(px[i], c[i]);
        mid[i] = __hmax2(pm[i], __hmin2(px[i], c[i]));
    }
    float* op = optr + lane * MP_TX;
    #pragma unroll
    for (int j = 0; j < 8; j += 2) {
        float4 ov;
        {
            __half2 loS = h2shift(lo[j],  lo[j + 1]);
            __half2 miS = h2shift(mid[j], mid[j + 1]);
            __half2 hiS = h2shift(hi[j],  hi[j + 1]);
            __half2 mxlo = __hmax2(__hmax2(lo[j], loS), lo[j + 1]);
            __half2 mnhi = __hmin2(__hmin2(hi[j], hiS), hi[j + 1]);
            __half2 mdmi = h2med3(mid[j], miS, mid[j + 1]);
            __half2 res  = h2med3(mxlo, mdmi, mnhi);
            ov.x = __low2float(res); ov.y = __high2float(res);
        }
        {
            __half2 loS = h2shift(lo[j + 1],  lo[j + 2]);
            __half2 miS = h2shift(mid[j + 1], mid[j + 2]);
            __half2 hiS = h2shift(hi[j + 1],  hi[j + 2]);
            __half2 mxlo = __hmax2(__hmax2(lo[j + 1], loS), lo[j + 2]);
            __half2 mnhi = __hmin2(__hmin2(hi[j + 1], hiS), hi[j + 2]);
            __half2 mdmi = h2med3(mid[j + 1], miS, mid[j + 2]);
            __half2 res  = h2med3(mxlo, mdmi, mnhi);
            ov.z = __low2float(res); ov.w = __high2float(res);
        }
        *(float4*)(op + 2 * j) = ov;
    }
}

__global__ __launch_bounds__(MP_BLK, 8)
void median3x3_v9(const float* __restrict__ in, float* __restrict__ out) {
    const int wid  = blockIdx.x * (MP_BLK / 32) + (threadIdx.x >> 5);
    const int lane = threadIdx.x & 31;
    const int yb   = wid & (MP_RP - 1);   // row-pair within channel
    const int bc   = wid >> 8;            // image-channel
    const int y0   = yb * 2;

    const float* rowa = in + (size_t)bc * (MP_H * MP_W) + (size_t)y0 * MP_W;
    float* ob = out + (size_t)bc * (MP_H * MP_W) + (size_t)y0 * MP_W;

    __half2 a[MP_NP], b[MP_NP], rm[MP_NP];

    mp_load_row_h2(rowa, lane, a);
    mp_load_row_h2(rowa + MP_W, lane, b);
    if (y0 > 0) {
        mp_load_row_h2(rowa - MP_W, lane, rm);
    } else {
        #pragma unroll
        for (int i = 0; i < MP_NP; i++) rm[i] = __half2half2(__float2half(0.0f));
    }

    // Shared vertical pair of both windows.
    __half2 pm[MP_NP], px[MP_NP];
    #pragma unroll
    for (int i = 0; i < MP_NP; i++) {
        pm[i] = __hmin2(a[i], b[i]);
        px[i] = __hmax2(a[i], b[i]);
    }

    mp_emit_row(pm, px, rm, ob, lane);          // output row y0 (third = y0-1)

    __half2 rp[MP_NP];
    if (y0 + 2 < MP_H) {
        mp_load_row_h2(rowa + 2 * MP_W, lane, rp);
    } else {
        #pragma unroll
        for (int i = 0; i < MP_NP; i++) rp[i] = __half2half2(__float2half(0.0f));
    }

    mp_emit_row(pm, px, rp, ob + MP_W, lane);   // output row y0+1 (third = y0+2)
}

extern "C" void kernel_launch(void* const* d_in, const int* in_sizes, int n_in,
                              void* d_out, int out_size) {
    (void)in_sizes; (void)n_in; (void)out_size;
    const float* x = (const float*)d_in[0];
    float* out = (float*)d_out;
    const int total_warps = MP_BC * MP_RP;                 // 12288 warps
    median3x3_v9<<<total_warps / 4, MP_BLK>>>(x, out);     // 3072 CTAs
}

// round 17
// speedup vs baseline: 1.3575x; 1.3575x over previous
#include <cuda_runtime.h>
#include <cuda_bf16.h>
#include <cuda_fp16.h>

// MedianPool2d 3x3, zero padding, x: [16, 3, 512, 512] fp32.
// v10: v8's packed-fp16x2 comparator tree + TY=4 (two shared vertical pairs).
// TX=8/lane, warp = contiguous 256 px (32B lane stride, proven v8 pattern).
// Windows (ym,y0,y1),(y0,y1,y2),(y1,y2,y3),(y2,y3,y4) via pairs (y0,y1),
// (y2,y3): each window = one 3-op packed insert. Row loads: 1.5/output row.
// Exact-in-fp16 median-of-9: med3( max3(lo), med3(mid), min3(hi) ).

#define MP_W 512
#define MP_H 512
#define MP_BC 48            // 16 * 3
#define MP_TX 8             // pixels per thread (horizontal)
#define MP_SEGS 64          // MP_W / MP_TX
#define MP_BANDS 128        // MP_H / 4
#define MP_NP 5             // packed half2 regs per row
#define MP_BLK 128

// Load row segment [xs-1, xs+8] (fp32) and pack to 5 half2: {c-1,c0}..{c7,c8}.
__device__ __forceinline__ void mp_load_row_h2(const float* __restrict__ row,
                                               int xs, int lane, __half2 v[MP_NP]) {
    float4 a = *(const float4*)(row + xs);
    float4 b = *(const float4*)(row + xs + 4);
    float left  = __shfl_up_sync(0xffffffffu, b.w, 1);   // prev seg's col 7
    float right = __shfl_down_sync(0xffffffffu, a.x, 1); // next seg's col 0
    if (lane == 0)  left  = (xs > 0)            ? __ldg(row + xs - 1)     : 0.0f;
    if (lane == 31) right = (xs + MP_TX < MP_W) ? __ldg(row + xs + MP_TX) : 0.0f;
    v[0] = __floats2half2_rn(left, a.x);
    v[1] = __floats2half2_rn(a.y,  a.z);
    v[2] = __floats2half2_rn(a.w,  b.x);
    v[3] = __floats2half2_rn(b.y,  b.z);
    v[4] = __floats2half2_rn(b.w,  right);
}

__device__ __forceinline__ __half2 h2med3(__half2 a, __half2 b, __half2 c) {
    return __hmax2(__hmin2(a, b), __hmin2(__hmax2(a, b), c));
}

// {a.hi, b.lo}
__device__ __forceinline__ __half2 h2shift(__half2 a, __half2 b) {
    return __halves2half2(__high2half(a), __low2half(b));
}

// One output row: insert third row c into shared vertical pair (pm, px),
// packed horizontal combine, fp32 store of 8 px.
__device__ __forceinline__ void mp_emit_row(const __half2 pm[MP_NP],
                                            const __half2 px[MP_NP],
                                            const __half2 c[MP_NP],
                                            float* optr) {
    __half2 lo[MP_NP], mid[MP_NP], hi[MP_NP];
    #pragma unroll
    for (int i = 0; i < MP_NP; i++) {
        lo[i]  = __hmin2(pm[i], c[i]);
        hi[i]  = __hmax2(px[i], c[i]);
        mid[i] = __hmax2(pm[i], __hmin2(px[i], c[i]));
    }
    float o[MP_TX];
    #pragma unroll
    for (int j = 0; j < 4; j++) {
        __half2 loS = h2shift(lo[j],  lo[j + 1]);
        __half2 miS = h2shift(mid[j], mid[j + 1]);
        __half2 hiS = h2shift(hi[j],  hi[j + 1]);
        __half2 mxlo = __hmax2(__hmax2(lo[j],  loS), lo[j + 1]);
        __half2 mnhi = __hmin2(__hmin2(hi[j],  hiS), hi[j + 1]);
        __half2 mdmi = h2med3(mid[j], miS, mid[j + 1]);
        __half2 res  = h2med3(mxlo, mdmi, mnhi);
        o[2 * j]     = __low2float(res);
        o[2 * j + 1] = __high2float(res);
    }
    *(float4*)(optr)     = make_float4(o[0], o[1], o[2], o[3]);
    *(float4*)(optr + 4) = make_float4(o[4], o[5], o[6], o[7]);
}

__global__ __launch_bounds__(MP_BLK, 8)
void median3x3_v10(const float* __restrict__ in, float* __restrict__ out) {
    const int gid  = blockIdx.x * MP_BLK + threadIdx.x;
    const int lane = threadIdx.x & 31;
    const int seg  = gid & (MP_SEGS - 1);          // bits [0,6)
    const int yb   = (gid >> 6) & (MP_BANDS - 1);  // bits [6,13)
    const int bc   = gid >> 13;                    // bits [13,...)
    const int xs   = seg * MP_TX;
    const int y0   = yb * 4;

    const float* rowa = in + (size_t)bc * (MP_H * MP_W) + (size_t)y0 * MP_W;
    float* ob = out + (size_t)bc * (MP_H * MP_W) + (size_t)y0 * MP_W + xs;

    __half2 rm[MP_NP], r0[MP_NP], r1[MP_NP], t[MP_NP];

    // ---- rows ym, y0, y1 ----
    mp_load_row_h2(rowa, xs, lane, r0);
    mp_load_row_h2(rowa + MP_W, xs, lane, r1);
    if (y0 > 0) {
        mp_load_row_h2(rowa - MP_W, xs, lane, rm);
    } else {
        #pragma unroll
        for (int i = 0; i < MP_NP; i++) rm[i] = __half2half2(__float2half(0.0f));
    }

    // pair (y0, y1)
    __half2 pm[MP_NP], px[MP_NP];
    #pragma unroll
    for (int i = 0; i < MP_NP; i++) {
        pm[i] = __hmin2(r0[i], r1[i]);
        px[i] = __hmax2(r0[i], r1[i]);
    }

    mp_emit_row(pm, px, rm, ob);               // w0: (ym, y0, y1)

    // ---- row y2 (always valid: y0+2 <= 510) ----
    mp_load_row_h2(rowa + 2 * MP_W, xs, lane, t);
    mp_emit_row(pm, px, t, ob + MP_W);         // w1: (y0, y1, y2)

    // ---- row y3 (always valid: y0+3 <= 511), pair (y2, y3) ----
    mp_load_row_h2(rowa + 3 * MP_W, xs, lane, rm);  // reuse rm for y3
    #pragma unroll
    for (int i = 0; i < MP_NP; i++) {
        pm[i] = __hmin2(t[i], rm[i]);
        px[i] = __hmax2(t[i], rm[i]);
    }
    mp_emit_row(pm, px, r1, ob + 2 * MP_W);    // w2: (y1, y2, y3)

    // ---- row y4 (bottom band: zero pad) ----
    if (y0 + 4 < MP_H) {
        mp_load_row_h2(rowa + 4 * MP_W, xs, lane, r0);  // reuse r0 for y4
    } else {
        #pragma unroll
        for (int i = 0; i < MP_NP; i++) r0[i] = __half2half2(__float2half(0.0f));
    }
    mp_emit_row(pm, px, r0, ob + 3 * MP_W);    // w3: (y2, y3, y4)
}

extern "C" void kernel_launch(void* const* d_in, const int* in_sizes, int n_in,
                              void* d_out, int out_size) {
    (void)in_sizes; (void)n_in; (void)out_size;
    const float* x = (const float*)d_in[0];
    float* out = (float*)d_out;
    const int total_threads = MP_BC * MP_BANDS * MP_SEGS;       // 393,216
    median3x3_v10<<<total_threads / MP_BLK, MP_BLK>>>(x, out);  // 3072 CTAs
}